// round 1
// baseline (speedup 1.0000x reference)
#include <cuda_runtime.h>
#include <math.h>
#include <math_constants.h>

// Problem constants
#define Bq 16
#define Nq 256
#define Dq 256
#define Hq 8
#define HDq 32
#define PDq 4
#define RATIOq 4
#define ROWS (Bq*Nq)          // 4096
#define DFF (RATIOq*Dq)       // 1024

// ---------------- scratch (device globals; no allocation allowed) -------------
__device__ float g_bias[(size_t)Bq*Hq*Nq*Nq];   // [B,H,N,N]  8,388,608
__device__ float g_xn[(size_t)ROWS*Dq];         // layernorm output (reused twice)
__device__ float g_qkv[(size_t)ROWS*3*Dq];      // [B,N,3,H,HD]
__device__ float g_attout[(size_t)ROWS*Dq];     // [B,N,D]
__device__ float g_x2[(size_t)ROWS*Dq];         // x + proj(attn)
__device__ float g_hid[(size_t)ROWS*DFF];       // mlp hidden

__device__ __forceinline__ float gelu_f(float x) {
    return 0.5f * x * (1.0f + erff(x * 0.70710678118654752f));
}

// ---------------- Kernel 1: pairwise bias MLP --------------------------------
// u [B,N,N,4] -> bias [B,H,N,N].  One thread per (b,i,j).
__global__ void __launch_bounds__(256, 2) pairwise_kernel(
    const float* __restrict__ u,
    const float* __restrict__ w1, const float* __restrict__ b1,
    const float* __restrict__ w2, const float* __restrict__ b2,
    const float* __restrict__ w3, const float* __restrict__ b3)
{
    __shared__ float w1s[4*64];
    __shared__ float b1s[64];
    __shared__ float w2t[64*64];   // transposed: w2t[k][j] = w2[j][k]
    __shared__ float b2s[64];
    __shared__ float w3s[64*8];
    __shared__ float b3s[8];

    int tid = threadIdx.x;
    w1s[tid] = w1[tid];
    if (tid < 64) { b1s[tid] = b1[tid]; b2s[tid] = b2[tid]; }
    #pragma unroll
    for (int i = tid; i < 4096; i += 256) {
        int j = i >> 6, k = i & 63;
        w2t[k*64 + j] = w2[i];
    }
    w3s[tid]       = w3[tid];
    w3s[tid + 256] = w3[tid + 256];
    if (tid < 8) b3s[tid] = b3[tid];
    __syncthreads();

    int idx = blockIdx.x * 256 + tid;     // 0 .. B*N*N-1
    float4 uv = reinterpret_cast<const float4*>(u)[idx];

    float h1[64];
    #pragma unroll
    for (int k = 0; k < 64; k++) {
        float a = b1s[k];
        a = fmaf(uv.x, w1s[k],       a);
        a = fmaf(uv.y, w1s[64 + k],  a);
        a = fmaf(uv.z, w1s[128 + k], a);
        a = fmaf(uv.w, w1s[192 + k], a);
        h1[k] = gelu_f(a);
    }

    float out[8];
    #pragma unroll
    for (int h = 0; h < 8; h++) out[h] = b3s[h];

    // layer2 (64x64) fused with layer3 (64x8): k rolled, j fully unrolled
    for (int k = 0; k < 64; k++) {
        float acc = b2s[k];
        const float4* wr = reinterpret_cast<const float4*>(&w2t[k*64]);
        #pragma unroll
        for (int jj = 0; jj < 16; jj++) {
            float4 w = wr[jj];
            acc = fmaf(h1[4*jj+0], w.x, acc);
            acc = fmaf(h1[4*jj+1], w.y, acc);
            acc = fmaf(h1[4*jj+2], w.z, acc);
            acc = fmaf(h1[4*jj+3], w.w, acc);
        }
        float g = gelu_f(acc);
        float4 wa = *reinterpret_cast<const float4*>(&w3s[k*8]);
        float4 wb = *reinterpret_cast<const float4*>(&w3s[k*8 + 4]);
        out[0] = fmaf(g, wa.x, out[0]);
        out[1] = fmaf(g, wa.y, out[1]);
        out[2] = fmaf(g, wa.z, out[2]);
        out[3] = fmaf(g, wa.w, out[3]);
        out[4] = fmaf(g, wb.x, out[4]);
        out[5] = fmaf(g, wb.y, out[5]);
        out[6] = fmaf(g, wb.z, out[6]);
        out[7] = fmaf(g, wb.w, out[7]);
    }

    int b = idx >> 16;
    int i = (idx >> 8) & 255;
    int j = idx & 255;
    size_t base = (size_t)b * Hq * 65536 + (size_t)i * 256 + j;
    #pragma unroll
    for (int h = 0; h < 8; h++)
        g_bias[base + (size_t)h * 65536] = gelu_f(out[h]);
}

// ---------------- Kernel 2: LayerNorm (warp per row, D=256) ------------------
__global__ void ln_kernel(const float* __restrict__ x,
                          const float* __restrict__ gg, const float* __restrict__ bb,
                          float* __restrict__ y)
{
    int w = threadIdx.x >> 5, lane = threadIdx.x & 31;
    int row = blockIdx.x * 8 + w;
    const float4* xr = reinterpret_cast<const float4*>(x + (size_t)row * 256);
    float4 a = xr[lane*2], c = xr[lane*2 + 1];
    float s = a.x + a.y + a.z + a.w + c.x + c.y + c.z + c.w;
    #pragma unroll
    for (int o = 16; o; o >>= 1) s += __shfl_xor_sync(0xffffffffu, s, o);
    float mu = s * (1.0f / 256.0f);
    float dx[8] = {a.x-mu, a.y-mu, a.z-mu, a.w-mu, c.x-mu, c.y-mu, c.z-mu, c.w-mu};
    float ss = 0.f;
    #pragma unroll
    for (int q = 0; q < 8; q++) ss += dx[q]*dx[q];
    #pragma unroll
    for (int o = 16; o; o >>= 1) ss += __shfl_xor_sync(0xffffffffu, ss, o);
    float rstd = rsqrtf(ss * (1.0f/256.0f) + 1e-5f);
    const float4* gr = reinterpret_cast<const float4*>(gg);
    const float4* br = reinterpret_cast<const float4*>(bb);
    float4 g0 = gr[lane*2], g1 = gr[lane*2+1];
    float4 b0 = br[lane*2], b1 = br[lane*2+1];
    float4 o0, o1;
    o0.x = fmaf(dx[0]*rstd, g0.x, b0.x); o0.y = fmaf(dx[1]*rstd, g0.y, b0.y);
    o0.z = fmaf(dx[2]*rstd, g0.z, b0.z); o0.w = fmaf(dx[3]*rstd, g0.w, b0.w);
    o1.x = fmaf(dx[4]*rstd, g1.x, b1.x); o1.y = fmaf(dx[5]*rstd, g1.y, b1.y);
    o1.z = fmaf(dx[6]*rstd, g1.z, b1.z); o1.w = fmaf(dx[7]*rstd, g1.w, b1.w);
    float4* yr = reinterpret_cast<float4*>(y + (size_t)row * 256);
    yr[lane*2] = o0; yr[lane*2 + 1] = o1;
}

// ---------------- Kernel 3: tiled SGEMM  C = act(A@W + bias) (+res) ----------
// A [M,K] rm, W [K,Nc] rm. BM=BN=64, BK=16, 256 thr, 4x4 per thread.
template<int ACT, bool RES>
__global__ void __launch_bounds__(256) gemm_kernel(
    const float* __restrict__ A, const float* __restrict__ W,
    const float* __restrict__ bias, const float* __restrict__ res,
    float* __restrict__ C, int K, int Nc)
{
    __shared__ float As[16][64];
    __shared__ float Ws[16][64];
    int tid = threadIdx.x;
    int tx = tid & 15, ty = tid >> 4;
    int row0 = blockIdx.y * 64, col0 = blockIdx.x * 64;

    float acc[4][4];
    #pragma unroll
    for (int i = 0; i < 4; i++)
        #pragma unroll
        for (int j = 0; j < 4; j++) acc[i][j] = 0.f;

    int ar = tid >> 2;          // 0..63
    int ac = (tid & 3) * 4;     // 0,4,8,12
    int wr = tid >> 4;          // 0..15
    int wc = (tid & 15) * 4;    // 0..60
    const float* Ap = A + (size_t)(row0 + ar) * K + ac;
    const float* Wp = W + (size_t)wr * Nc + col0 + wc;

    for (int kt = 0; kt < K; kt += 16) {
        float4 a = *reinterpret_cast<const float4*>(Ap + kt);
        As[ac+0][ar] = a.x; As[ac+1][ar] = a.y; As[ac+2][ar] = a.z; As[ac+3][ar] = a.w;
        float4 w = *reinterpret_cast<const float4*>(Wp + (size_t)kt * Nc);
        *reinterpret_cast<float4*>(&Ws[wr][wc]) = w;
        __syncthreads();
        #pragma unroll
        for (int kk = 0; kk < 16; kk++) {
            float4 a4 = *reinterpret_cast<const float4*>(&As[kk][ty*4]);
            float4 w4 = *reinterpret_cast<const float4*>(&Ws[kk][tx*4]);
            float af[4] = {a4.x, a4.y, a4.z, a4.w};
            float wf[4] = {w4.x, w4.y, w4.z, w4.w};
            #pragma unroll
            for (int i = 0; i < 4; i++)
                #pragma unroll
                for (int j = 0; j < 4; j++)
                    acc[i][j] = fmaf(af[i], wf[j], acc[i][j]);
        }
        __syncthreads();
    }

    #pragma unroll
    for (int i = 0; i < 4; i++) {
        int r = row0 + ty*4 + i;
        #pragma unroll
        for (int j = 0; j < 4; j++) {
            int cc = col0 + tx*4 + j;
            float v = acc[i][j] + bias[cc];
            if (ACT == 1) v = gelu_f(v);
            if (RES)      v += res[(size_t)r * Nc + cc];
            C[(size_t)r * Nc + cc] = v;
        }
    }
}

// ---------------- Kernel 4: fused attention ----------------------------------
// One block per (b,h). K/V staged in smem; softmax(QK^T/sqrt(HD)+bias) @ V.
__global__ void attn_kernel(const unsigned char* __restrict__ mask)
{
    extern __shared__ float sm[];
    float* kT = sm;                   // [32][256]  kT[hd*256 + j]
    float* vS = sm + 32*256;          // [256][33]  vS[j*33 + hd]
    float* pS = vS + 256*33;          // [8][256]

    int bh = blockIdx.x;
    int b = bh >> 3, h = bh & 7;
    int tid = threadIdx.x;
    int w = tid >> 5, lane = tid & 31;

    // stage K (transposed) and V
    const float* kp = g_qkv + ((size_t)(b*256 + tid)) * 768 + 256 + h*32;
    const float* vp = kp + 256;
    #pragma unroll
    for (int q = 0; q < 8; q++) {
        float4 kv = *reinterpret_cast<const float4*>(kp + q*4);
        kT[(q*4+0)*256 + tid] = kv.x;
        kT[(q*4+1)*256 + tid] = kv.y;
        kT[(q*4+2)*256 + tid] = kv.z;
        kT[(q*4+3)*256 + tid] = kv.w;
        float4 vv = *reinterpret_cast<const float4*>(vp + q*4);
        vS[tid*33 + q*4 + 0] = vv.x;
        vS[tid*33 + q*4 + 1] = vv.y;
        vS[tid*33 + q*4 + 2] = vv.z;
        vS[tid*33 + q*4 + 3] = vv.w;
    }
    __syncthreads();

    const float isq = 0.17677669529663689f;   // 1/sqrt(32)
    const unsigned char* mp = mask + b*256;
    uchar4 m0 = *reinterpret_cast<const uchar4*>(mp + lane*4);
    uchar4 m1 = *reinterpret_cast<const uchar4*>(mp + 128 + lane*4);

    for (int t = 0; t < 32; t++) {
        int i = t * 8 + w;
        const float* qp = g_qkv + ((size_t)(b*256 + i)) * 768 + h*32;
        float qr[32];
        #pragma unroll
        for (int q = 0; q < 8; q++) {
            float4 f = *reinterpret_cast<const float4*>(qp + q*4);
            qr[q*4+0] = f.x; qr[q*4+1] = f.y; qr[q*4+2] = f.z; qr[q*4+3] = f.w;
        }
        float acc[8];
        #pragma unroll
        for (int c = 0; c < 8; c++) acc[c] = 0.f;
        #pragma unroll
        for (int hd = 0; hd < 32; hd++) {
            float qh = qr[hd];
            float4 k0 = *reinterpret_cast<const float4*>(&kT[hd*256 + lane*4]);
            float4 k1 = *reinterpret_cast<const float4*>(&kT[hd*256 + 128 + lane*4]);
            acc[0] = fmaf(qh, k0.x, acc[0]); acc[1] = fmaf(qh, k0.y, acc[1]);
            acc[2] = fmaf(qh, k0.z, acc[2]); acc[3] = fmaf(qh, k0.w, acc[3]);
            acc[4] = fmaf(qh, k1.x, acc[4]); acc[5] = fmaf(qh, k1.y, acc[5]);
            acc[6] = fmaf(qh, k1.z, acc[6]); acc[7] = fmaf(qh, k1.w, acc[7]);
        }
        const float* bp = g_bias + ((size_t)bh * 256 + i) * 256;
        float4 bb0 = *reinterpret_cast<const float4*>(bp + lane*4);
        float4 bb1 = *reinterpret_cast<const float4*>(bp + 128 + lane*4);
        float l[8];
        l[0] = fmaf(acc[0], isq, bb0.x); l[1] = fmaf(acc[1], isq, bb0.y);
        l[2] = fmaf(acc[2], isq, bb0.z); l[3] = fmaf(acc[3], isq, bb0.w);
        l[4] = fmaf(acc[4], isq, bb1.x); l[5] = fmaf(acc[5], isq, bb1.y);
        l[6] = fmaf(acc[6], isq, bb1.z); l[7] = fmaf(acc[7], isq, bb1.w);
        if (m0.x) l[0] = -CUDART_INF_F; if (m0.y) l[1] = -CUDART_INF_F;
        if (m0.z) l[2] = -CUDART_INF_F; if (m0.w) l[3] = -CUDART_INF_F;
        if (m1.x) l[4] = -CUDART_INF_F; if (m1.y) l[5] = -CUDART_INF_F;
        if (m1.z) l[6] = -CUDART_INF_F; if (m1.w) l[7] = -CUDART_INF_F;

        float mx = l[0];
        #pragma unroll
        for (int c = 1; c < 8; c++) mx = fmaxf(mx, l[c]);
        #pragma unroll
        for (int o = 16; o; o >>= 1) mx = fmaxf(mx, __shfl_xor_sync(0xffffffffu, mx, o));
        float e[8], s = 0.f;
        #pragma unroll
        for (int c = 0; c < 8; c++) { e[c] = expf(l[c] - mx); s += e[c]; }
        #pragma unroll
        for (int o = 16; o; o >>= 1) s += __shfl_xor_sync(0xffffffffu, s, o);
        float inv = 1.0f / s;
        float4 p0 = make_float4(e[0]*inv, e[1]*inv, e[2]*inv, e[3]*inv);
        float4 p1 = make_float4(e[4]*inv, e[5]*inv, e[6]*inv, e[7]*inv);
        *reinterpret_cast<float4*>(&pS[w*256 + lane*4])       = p0;
        *reinterpret_cast<float4*>(&pS[w*256 + 128 + lane*4]) = p1;
        __syncwarp();

        // PV: lane = hd
        float oacc = 0.f;
        #pragma unroll 8
        for (int j4 = 0; j4 < 64; j4++) {
            float4 p = *reinterpret_cast<const float4*>(&pS[w*256 + j4*4]);
            oacc = fmaf(p.x, vS[(j4*4+0)*33 + lane], oacc);
            oacc = fmaf(p.y, vS[(j4*4+1)*33 + lane], oacc);
            oacc = fmaf(p.z, vS[(j4*4+2)*33 + lane], oacc);
            oacc = fmaf(p.w, vS[(j4*4+3)*33 + lane], oacc);
        }
        g_attout[((size_t)(b*256 + i)) * 256 + h*32 + lane] = oacc;
        __syncwarp();
    }
}

// ---------------- launch ------------------------------------------------------
extern "C" void kernel_launch(void* const* d_in, const int* in_sizes, int n_in,
                              void* d_out, int out_size)
{
    const float* x      = (const float*)d_in[0];
    const float* u      = (const float*)d_in[1];
    const unsigned char* mask = (const unsigned char*)d_in[2];
    const float* n1_g   = (const float*)d_in[3];
    const float* n1_b   = (const float*)d_in[4];
    const float* qkv_w  = (const float*)d_in[5];
    const float* qkv_b  = (const float*)d_in[6];
    const float* proj_w = (const float*)d_in[7];
    const float* proj_b = (const float*)d_in[8];
    const float* n2_g   = (const float*)d_in[9];
    const float* n2_b   = (const float*)d_in[10];
    const float* mlp_w1 = (const float*)d_in[11];
    const float* mlp_b1 = (const float*)d_in[12];
    const float* mlp_w2 = (const float*)d_in[13];
    const float* mlp_b2 = (const float*)d_in[14];
    const float* pw_w1  = (const float*)d_in[15];
    const float* pw_b1  = (const float*)d_in[16];
    const float* pw_w2  = (const float*)d_in[17];
    const float* pw_b2  = (const float*)d_in[18];
    const float* pw_w3  = (const float*)d_in[19];
    const float* pw_b3  = (const float*)d_in[20];
    float* out = (float*)d_out;

    float* xn  = nullptr; float* qkv = nullptr; float* ao = nullptr;
    float* x2  = nullptr; float* hid = nullptr;
    cudaGetSymbolAddress((void**)&xn,  g_xn);
    cudaGetSymbolAddress((void**)&qkv, g_qkv);
    cudaGetSymbolAddress((void**)&ao,  g_attout);
    cudaGetSymbolAddress((void**)&x2,  g_x2);
    cudaGetSymbolAddress((void**)&hid, g_hid);

    // 1) pairwise bias MLP
    pairwise_kernel<<<Bq*Nq*Nq/256, 256>>>(u, pw_w1, pw_b1, pw_w2, pw_b2, pw_w3, pw_b3);

    // 2) LN1 + qkv GEMM
    ln_kernel<<<ROWS/8, 256>>>(x, n1_g, n1_b, xn);
    {
        dim3 grid(3*Dq/64, ROWS/64);
        gemm_kernel<0,false><<<grid, 256>>>(xn, qkv_w, qkv_b, nullptr, qkv, Dq, 3*Dq);
    }

    // 3) attention (needs >48KB dynamic smem)
    {
        int smem = (32*256 + 256*33 + 8*256) * (int)sizeof(float);
        cudaFuncSetAttribute(attn_kernel, cudaFuncAttributeMaxDynamicSharedMemorySize, smem);
        attn_kernel<<<Bq*Hq, 256, smem>>>(mask);
    }

    // 4) proj + residual
    {
        dim3 grid(Dq/64, ROWS/64);
        gemm_kernel<0,true><<<grid, 256>>>(ao, proj_w, proj_b, x, x2, Dq, Dq);
    }

    // 5) LN2 + MLP
    ln_kernel<<<ROWS/8, 256>>>(x2, n2_g, n2_b, xn);
    {
        dim3 grid(DFF/64, ROWS/64);
        gemm_kernel<1,false><<<grid, 256>>>(xn, mlp_w1, mlp_b1, nullptr, hid, Dq, DFF);
    }
    {
        dim3 grid(Dq/64, ROWS/64);
        gemm_kernel<1,true><<<grid, 256>>>(hid, mlp_w2, mlp_b2, x2, out, DFF, Dq);
    }
}

// round 4
// speedup vs baseline: 1.1583x; 1.1583x over previous
#include <cuda_runtime.h>
#include <cstdint>
#include <math.h>
#include <math_constants.h>

// Problem constants
#define Bq 16
#define Nq 256
#define Dq 256
#define Hq 8
#define HDq 32
#define PDq 4
#define RATIOq 4
#define ROWS (Bq*Nq)          // 4096
#define DFF (RATIOq*Dq)       // 1024

// ---------------- scratch (device globals; no allocation allowed) -------------
__device__ float g_bias[(size_t)Bq*Hq*Nq*Nq];   // [B,H,N,N]
__device__ float g_xn[(size_t)ROWS*Dq];
__device__ float g_qkv[(size_t)ROWS*3*Dq];      // [B,N,3,H,HD]
__device__ float g_attout[(size_t)ROWS*Dq];
__device__ float g_x2[(size_t)ROWS*Dq];
__device__ float g_hid[(size_t)ROWS*DFF];

__device__ __forceinline__ float gelu_f(float x) {
    return 0.5f * x * (1.0f + erff(x * 0.70710678118654752f));
}

__device__ __forceinline__ float tf32r(float x) {
    uint32_t o;
    asm("cvt.rna.tf32.f32 %0, %1;" : "=r"(o) : "f"(x));
    return __uint_as_float(o);
}

__device__ __forceinline__ void mma_tf32(float c[4],
    uint32_t a0, uint32_t a1, uint32_t a2, uint32_t a3,
    uint32_t b0, uint32_t b1)
{
    asm("mma.sync.aligned.m16n8k8.row.col.f32.tf32.tf32.f32 "
        "{%0,%1,%2,%3}, {%4,%5,%6,%7}, {%8,%9}, {%0,%1,%2,%3};\n"
        : "+f"(c[0]), "+f"(c[1]), "+f"(c[2]), "+f"(c[3])
        : "r"(a0), "r"(a1), "r"(a2), "r"(a3), "r"(b0), "r"(b1));
}

// ---------------- Kernel 1: pairwise bias MLP (tf32 tensor core layer-2) -----
// u [B,N,N,4] -> bias [B,H,N,N].  Block = 256 positions; warp owns 32 rows.
// dyn smem: w2s [64][72] tf32, h1s [256][68] tf32
#define W2_STR 72
#define H1_STR 68
__global__ void __launch_bounds__(256, 2) pairwise_kernel(
    const float* __restrict__ u,
    const float* __restrict__ w1, const float* __restrict__ b1,
    const float* __restrict__ w2, const float* __restrict__ b2,
    const float* __restrict__ w3, const float* __restrict__ b3)
{
    extern __shared__ float sm[];
    float* w2s = sm;                    // 64*72
    float* h1s = sm + 64*W2_STR;        // 256*68

    __shared__ float w1s[4*64];
    __shared__ float b1s[64];
    __shared__ float b2s[64];
    __shared__ float w3s[64*8];
    __shared__ float b3s[8];

    int tid = threadIdx.x;
    int lane = tid & 31, w = tid >> 5;
    int tg = lane >> 2;      // t/4
    int tr = lane & 3;       // t%4

    // load weights
    w1s[tid] = w1[tid];
    if (tid < 64) { b1s[tid] = b1[tid]; b2s[tid] = b2[tid]; }
    w3s[tid] = w3[tid]; w3s[tid + 256] = w3[tid + 256];
    if (tid < 8) b3s[tid] = b3[tid];
    #pragma unroll
    for (int i = tid; i < 4096; i += 256) {
        int k = i >> 6, n = i & 63;
        w2s[k*W2_STR + n] = tf32r(w2[i]);
    }
    __syncthreads();

    // ---- layer 1 (scalar): one position per thread -> h1s (tf32-rounded)
    int pos0 = blockIdx.x * 256;
    float4 uv = reinterpret_cast<const float4*>(u)[pos0 + tid];
    #pragma unroll
    for (int k4 = 0; k4 < 16; k4++) {
        float4 hv;
        float* hp = &hv.x;
        #pragma unroll
        for (int q = 0; q < 4; q++) {
            int k = k4*4 + q;
            float a = b1s[k];
            a = fmaf(uv.x, w1s[k],       a);
            a = fmaf(uv.y, w1s[64 + k],  a);
            a = fmaf(uv.z, w1s[128 + k], a);
            a = fmaf(uv.w, w1s[192 + k], a);
            hp[q] = tf32r(gelu_f(a));
        }
        *reinterpret_cast<float4*>(&h1s[tid*H1_STR + k4*4]) = hv;
    }
    __syncwarp();   // warp reads only its own 32 rows

    // ---- layer 2 via mma + fused layer 3 partials
    int rbase = w * 32;
    float outA[4][8];    // rows: mt0-low, mt0-high, mt1-low, mt1-high
    #pragma unroll
    for (int r = 0; r < 4; r++)
        #pragma unroll
        for (int h = 0; h < 8; h++) outA[r][h] = 0.f;

    #pragma unroll
    for (int nt = 0; nt < 8; nt++) {
        float c[2][4];
        #pragma unroll
        for (int mt = 0; mt < 2; mt++)
            #pragma unroll
            for (int q = 0; q < 4; q++) c[mt][q] = 0.f;

        #pragma unroll
        for (int kt = 0; kt < 8; kt++) {
            uint32_t bf0 = __float_as_uint(w2s[(kt*8 + tr    )*W2_STR + nt*8 + tg]);
            uint32_t bf1 = __float_as_uint(w2s[(kt*8 + tr + 4)*W2_STR + nt*8 + tg]);
            #pragma unroll
            for (int mt = 0; mt < 2; mt++) {
                int r = rbase + mt*16 + tg;
                uint32_t a0 = __float_as_uint(h1s[ r     *H1_STR + kt*8 + tr    ]);
                uint32_t a1 = __float_as_uint(h1s[(r + 8)*H1_STR + kt*8 + tr    ]);
                uint32_t a2 = __float_as_uint(h1s[ r     *H1_STR + kt*8 + tr + 4]);
                uint32_t a3 = __float_as_uint(h1s[(r + 8)*H1_STR + kt*8 + tr + 4]);
                mma_tf32(c[mt], a0, a1, a2, a3, bf0, bf1);
            }
        }
        // layer 3 partials for this nt's columns
        #pragma unroll
        for (int cc = 0; cc < 2; cc++) {
            int n = nt*8 + 2*tr + cc;
            float b2n = b2s[n];
            float4 w3a = *reinterpret_cast<const float4*>(&w3s[n*8]);
            float4 w3b = *reinterpret_cast<const float4*>(&w3s[n*8 + 4]);
            #pragma unroll
            for (int mt = 0; mt < 2; mt++) {
                float glo = gelu_f(c[mt][cc]     + b2n);   // row tg
                float ghi = gelu_f(c[mt][cc + 2] + b2n);   // row tg+8
                float* olo = outA[mt*2 + 0];
                float* ohi = outA[mt*2 + 1];
                olo[0] = fmaf(glo, w3a.x, olo[0]); olo[1] = fmaf(glo, w3a.y, olo[1]);
                olo[2] = fmaf(glo, w3a.z, olo[2]); olo[3] = fmaf(glo, w3a.w, olo[3]);
                olo[4] = fmaf(glo, w3b.x, olo[4]); olo[5] = fmaf(glo, w3b.y, olo[5]);
                olo[6] = fmaf(glo, w3b.z, olo[6]); olo[7] = fmaf(glo, w3b.w, olo[7]);
                ohi[0] = fmaf(ghi, w3a.x, ohi[0]); ohi[1] = fmaf(ghi, w3a.y, ohi[1]);
                ohi[2] = fmaf(ghi, w3a.z, ohi[2]); ohi[3] = fmaf(ghi, w3a.w, ohi[3]);
                ohi[4] = fmaf(ghi, w3b.x, ohi[4]); ohi[5] = fmaf(ghi, w3b.y, ohi[5]);
                ohi[6] = fmaf(ghi, w3b.z, ohi[6]); ohi[7] = fmaf(ghi, w3b.w, ohi[7]);
            }
        }
    }

    // ---- reduce across the 4 threads sharing each row; write bias
    #pragma unroll
    for (int rr = 0; rr < 4; rr++) {
        int mt = rr >> 1, hi = rr & 1;
        int lpos = rbase + mt*16 + tg + hi*8;
        int pos = pos0 + lpos;
        #pragma unroll
        for (int h = 0; h < 8; h++) {
            float v = outA[rr][h];
            v += __shfl_xor_sync(0xffffffffu, v, 1);
            v += __shfl_xor_sync(0xffffffffu, v, 2);
            outA[rr][h] = v;
        }
        int b  = pos >> 16;
        int ij = pos & 65535;
        size_t base = ((size_t)b * 8) * 65536 + (size_t)ij;
        int h0 = 2*tr;
        g_bias[base + (size_t)(h0    )*65536] = gelu_f(outA[rr][h0    ] + b3s[h0    ]);
        g_bias[base + (size_t)(h0 + 1)*65536] = gelu_f(outA[rr][h0 + 1] + b3s[h0 + 1]);
    }
}

// ---------------- Kernel 2: LayerNorm (warp per row, D=256) ------------------
__global__ void ln_kernel(const float* __restrict__ x,
                          const float* __restrict__ gg, const float* __restrict__ bb,
                          float* __restrict__ y)
{
    int w = threadIdx.x >> 5, lane = threadIdx.x & 31;
    int row = blockIdx.x * 8 + w;
    const float4* xr = reinterpret_cast<const float4*>(x + (size_t)row * 256);
    float4 a = xr[lane*2], c = xr[lane*2 + 1];
    float s = a.x + a.y + a.z + a.w + c.x + c.y + c.z + c.w;
    #pragma unroll
    for (int o = 16; o; o >>= 1) s += __shfl_xor_sync(0xffffffffu, s, o);
    float mu = s * (1.0f / 256.0f);
    float dx[8] = {a.x-mu, a.y-mu, a.z-mu, a.w-mu, c.x-mu, c.y-mu, c.z-mu, c.w-mu};
    float ss = 0.f;
    #pragma unroll
    for (int q = 0; q < 8; q++) ss += dx[q]*dx[q];
    #pragma unroll
    for (int o = 16; o; o >>= 1) ss += __shfl_xor_sync(0xffffffffu, ss, o);
    float rstd = rsqrtf(ss * (1.0f/256.0f) + 1e-5f);
    const float4* gr = reinterpret_cast<const float4*>(gg);
    const float4* br = reinterpret_cast<const float4*>(bb);
    float4 g0 = gr[lane*2], g1 = gr[lane*2+1];
    float4 b0 = br[lane*2], b1 = br[lane*2+1];
    float4 o0, o1;
    o0.x = fmaf(dx[0]*rstd, g0.x, b0.x); o0.y = fmaf(dx[1]*rstd, g0.y, b0.y);
    o0.z = fmaf(dx[2]*rstd, g0.z, b0.z); o0.w = fmaf(dx[3]*rstd, g0.w, b0.w);
    o1.x = fmaf(dx[4]*rstd, g1.x, b1.x); o1.y = fmaf(dx[5]*rstd, g1.y, b1.y);
    o1.z = fmaf(dx[6]*rstd, g1.z, b1.z); o1.w = fmaf(dx[7]*rstd, g1.w, b1.w);
    float4* yr = reinterpret_cast<float4*>(y + (size_t)row * 256);
    yr[lane*2] = o0; yr[lane*2 + 1] = o1;
}

// ---------------- Kernel 3: tiled SGEMM  C = act(A@W + bias) (+res) ----------
template<int ACT, bool RES>
__global__ void __launch_bounds__(256) gemm_kernel(
    const float* __restrict__ A, const float* __restrict__ W,
    const float* __restrict__ bias, const float* __restrict__ res,
    float* __restrict__ C, int K, int Nc)
{
    __shared__ float As[16][64];
    __shared__ float Ws[16][64];
    int tid = threadIdx.x;
    int tx = tid & 15, ty = tid >> 4;
    int row0 = blockIdx.y * 64, col0 = blockIdx.x * 64;

    float acc[4][4];
    #pragma unroll
    for (int i = 0; i < 4; i++)
        #pragma unroll
        for (int j = 0; j < 4; j++) acc[i][j] = 0.f;

    int ar = tid >> 2;
    int ac = (tid & 3) * 4;
    int wr = tid >> 4;
    int wc = (tid & 15) * 4;
    const float* Ap = A + (size_t)(row0 + ar) * K + ac;
    const float* Wp = W + (size_t)wr * Nc + col0 + wc;

    for (int kt = 0; kt < K; kt += 16) {
        float4 a = *reinterpret_cast<const float4*>(Ap + kt);
        As[ac+0][ar] = a.x; As[ac+1][ar] = a.y; As[ac+2][ar] = a.z; As[ac+3][ar] = a.w;
        float4 w = *reinterpret_cast<const float4*>(Wp + (size_t)kt * Nc);
        *reinterpret_cast<float4*>(&Ws[wr][wc]) = w;
        __syncthreads();
        #pragma unroll
        for (int kk = 0; kk < 16; kk++) {
            float4 a4 = *reinterpret_cast<const float4*>(&As[kk][ty*4]);
            float4 w4 = *reinterpret_cast<const float4*>(&Ws[kk][tx*4]);
            float af[4] = {a4.x, a4.y, a4.z, a4.w};
            float wf[4] = {w4.x, w4.y, w4.z, w4.w};
            #pragma unroll
            for (int i = 0; i < 4; i++)
                #pragma unroll
                for (int j = 0; j < 4; j++)
                    acc[i][j] = fmaf(af[i], wf[j], acc[i][j]);
        }
        __syncthreads();
    }

    #pragma unroll
    for (int i = 0; i < 4; i++) {
        int r = row0 + ty*4 + i;
        #pragma unroll
        for (int j = 0; j < 4; j++) {
            int cc = col0 + tx*4 + j;
            float v = acc[i][j] + bias[cc];
            if (ACT == 1) v = gelu_f(v);
            if (RES)      v += res[(size_t)r * Nc + cc];
            C[(size_t)r * Nc + cc] = v;
        }
    }
}

// ---------------- Kernel 4: fused attention ----------------------------------
// blockIdx.x = (b,h), blockIdx.y = query chunk (4 chunks of 64 rows).
__global__ void attn_kernel(const unsigned char* __restrict__ mask)
{
    extern __shared__ float sm[];
    float* kT = sm;                   // [32][256]
    float* vS = sm + 32*256;          // [256][33]
    float* pS = vS + 256*33;          // [8][256]

    int bh = blockIdx.x;
    int b = bh >> 3, h = bh & 7;
    int tid = threadIdx.x;
    int w = tid >> 5, lane = tid & 31;

    const float* kp = g_qkv + ((size_t)(b*256 + tid)) * 768 + 256 + h*32;
    const float* vp = kp + 256;
    #pragma unroll
    for (int q = 0; q < 8; q++) {
        float4 kv = *reinterpret_cast<const float4*>(kp + q*4);
        kT[(q*4+0)*256 + tid] = kv.x;
        kT[(q*4+1)*256 + tid] = kv.y;
        kT[(q*4+2)*256 + tid] = kv.z;
        kT[(q*4+3)*256 + tid] = kv.w;
        float4 vv = *reinterpret_cast<const float4*>(vp + q*4);
        vS[tid*33 + q*4 + 0] = vv.x;
        vS[tid*33 + q*4 + 1] = vv.y;
        vS[tid*33 + q*4 + 2] = vv.z;
        vS[tid*33 + q*4 + 3] = vv.w;
    }
    __syncthreads();

    const float isq = 0.17677669529663689f;
    const unsigned char* mp = mask + b*256;
    uchar4 m0 = *reinterpret_cast<const uchar4*>(mp + lane*4);
    uchar4 m1 = *reinterpret_cast<const uchar4*>(mp + 128 + lane*4);

    int t0 = blockIdx.y * 8;
    for (int t = t0; t < t0 + 8; t++) {
        int i = t * 8 + w;
        const float* qp = g_qkv + ((size_t)(b*256 + i)) * 768 + h*32;
        float qr[32];
        #pragma unroll
        for (int q = 0; q < 8; q++) {
            float4 f = *reinterpret_cast<const float4*>(qp + q*4);
            qr[q*4+0] = f.x; qr[q*4+1] = f.y; qr[q*4+2] = f.z; qr[q*4+3] = f.w;
        }
        float acc[8];
        #pragma unroll
        for (int c = 0; c < 8; c++) acc[c] = 0.f;
        #pragma unroll
        for (int hd = 0; hd < 32; hd++) {
            float qh = qr[hd];
            float4 k0 = *reinterpret_cast<const float4*>(&kT[hd*256 + lane*4]);
            float4 k1 = *reinterpret_cast<const float4*>(&kT[hd*256 + 128 + lane*4]);
            acc[0] = fmaf(qh, k0.x, acc[0]); acc[1] = fmaf(qh, k0.y, acc[1]);
            acc[2] = fmaf(qh, k0.z, acc[2]); acc[3] = fmaf(qh, k0.w, acc[3]);
            acc[4] = fmaf(qh, k1.x, acc[4]); acc[5] = fmaf(qh, k1.y, acc[5]);
            acc[6] = fmaf(qh, k1.z, acc[6]); acc[7] = fmaf(qh, k1.w, acc[7]);
        }
        const float* bp = g_bias + ((size_t)bh * 256 + i) * 256;
        float4 bb0 = *reinterpret_cast<const float4*>(bp + lane*4);
        float4 bb1 = *reinterpret_cast<const float4*>(bp + 128 + lane*4);
        float l[8];
        l[0] = fmaf(acc[0], isq, bb0.x); l[1] = fmaf(acc[1], isq, bb0.y);
        l[2] = fmaf(acc[2], isq, bb0.z); l[3] = fmaf(acc[3], isq, bb0.w);
        l[4] = fmaf(acc[4], isq, bb1.x); l[5] = fmaf(acc[5], isq, bb1.y);
        l[6] = fmaf(acc[6], isq, bb1.z); l[7] = fmaf(acc[7], isq, bb1.w);
        if (m0.x) l[0] = -CUDART_INF_F; if (m0.y) l[1] = -CUDART_INF_F;
        if (m0.z) l[2] = -CUDART_INF_F; if (m0.w) l[3] = -CUDART_INF_F;
        if (m1.x) l[4] = -CUDART_INF_F; if (m1.y) l[5] = -CUDART_INF_F;
        if (m1.z) l[6] = -CUDART_INF_F; if (m1.w) l[7] = -CUDART_INF_F;

        float mx = l[0];
        #pragma unroll
        for (int c = 1; c < 8; c++) mx = fmaxf(mx, l[c]);
        #pragma unroll
        for (int o = 16; o; o >>= 1) mx = fmaxf(mx, __shfl_xor_sync(0xffffffffu, mx, o));
        float e[8], s = 0.f;
        #pragma unroll
        for (int c = 0; c < 8; c++) { e[c] = expf(l[c] - mx); s += e[c]; }
        #pragma unroll
        for (int o = 16; o; o >>= 1) s += __shfl_xor_sync(0xffffffffu, s, o);
        float inv = 1.0f / s;
        float4 p0 = make_float4(e[0]*inv, e[1]*inv, e[2]*inv, e[3]*inv);
        float4 p1 = make_float4(e[4]*inv, e[5]*inv, e[6]*inv, e[7]*inv);
        *reinterpret_cast<float4*>(&pS[w*256 + lane*4])       = p0;
        *reinterpret_cast<float4*>(&pS[w*256 + 128 + lane*4]) = p1;
        __syncwarp();

        float oacc = 0.f;
        #pragma unroll 8
        for (int j4 = 0; j4 < 64; j4++) {
            float4 p = *reinterpret_cast<const float4*>(&pS[w*256 + j4*4]);
            oacc = fmaf(p.x, vS[(j4*4+0)*33 + lane], oacc);
            oacc = fmaf(p.y, vS[(j4*4+1)*33 + lane], oacc);
            oacc = fmaf(p.z, vS[(j4*4+2)*33 + lane], oacc);
            oacc = fmaf(p.w, vS[(j4*4+3)*33 + lane], oacc);
        }
        g_attout[((size_t)(b*256 + i)) * 256 + h*32 + lane] = oacc;
        __syncwarp();
    }
}

// ---------------- launch ------------------------------------------------------
extern "C" void kernel_launch(void* const* d_in, const int* in_sizes, int n_in,
                              void* d_out, int out_size)
{
    const float* x      = (const float*)d_in[0];
    const float* u      = (const float*)d_in[1];
    const unsigned char* mask = (const unsigned char*)d_in[2];
    const float* n1_g   = (const float*)d_in[3];
    const float* n1_b   = (const float*)d_in[4];
    const float* qkv_w  = (const float*)d_in[5];
    const float* qkv_b  = (const float*)d_in[6];
    const float* proj_w = (const float*)d_in[7];
    const float* proj_b = (const float*)d_in[8];
    const float* n2_g   = (const float*)d_in[9];
    const float* n2_b   = (const float*)d_in[10];
    const float* mlp_w1 = (const float*)d_in[11];
    const float* mlp_b1 = (const float*)d_in[12];
    const float* mlp_w2 = (const float*)d_in[13];
    const float* mlp_b2 = (const float*)d_in[14];
    const float* pw_w1  = (const float*)d_in[15];
    const float* pw_b1  = (const float*)d_in[16];
    const float* pw_w2  = (const float*)d_in[17];
    const float* pw_b2  = (const float*)d_in[18];
    const float* pw_w3  = (const float*)d_in[19];
    const float* pw_b3  = (const float*)d_in[20];
    float* out = (float*)d_out;

    float* xn  = nullptr; float* qkv = nullptr; float* ao = nullptr;
    float* x2  = nullptr; float* hid = nullptr;
    cudaGetSymbolAddress((void**)&xn,  g_xn);
    cudaGetSymbolAddress((void**)&qkv, g_qkv);
    cudaGetSymbolAddress((void**)&ao,  g_attout);
    cudaGetSymbolAddress((void**)&x2,  g_x2);
    cudaGetSymbolAddress((void**)&hid, g_hid);

    // 1) pairwise bias MLP (tf32 mma)
    {
        int smem = (64*W2_STR + 256*H1_STR) * (int)sizeof(float);
        cudaFuncSetAttribute(pairwise_kernel, cudaFuncAttributeMaxDynamicSharedMemorySize, smem);
        pairwise_kernel<<<Bq*Nq*Nq/256, 256, smem>>>(u, pw_w1, pw_b1, pw_w2, pw_b2, pw_w3, pw_b3);
    }

    // 2) LN1 + qkv GEMM
    ln_kernel<<<ROWS/8, 256>>>(x, n1_g, n1_b, xn);
    {
        dim3 grid(3*Dq/64, ROWS/64);
        gemm_kernel<0,false><<<grid, 256>>>(xn, qkv_w, qkv_b, nullptr, qkv, Dq, 3*Dq);
    }

    // 3) attention
    {
        int smem = (32*256 + 256*33 + 8*256) * (int)sizeof(float);
        cudaFuncSetAttribute(attn_kernel, cudaFuncAttributeMaxDynamicSharedMemorySize, smem);
        dim3 grid(Bq*Hq, 4);
        attn_kernel<<<grid, 256, smem>>>(mask);
    }

    // 4) proj + residual
    {
        dim3 grid(Dq/64, ROWS/64);
        gemm_kernel<0,true><<<grid, 256>>>(ao, proj_w, proj_b, x, x2, Dq, Dq);
    }

    // 5) LN2 + MLP
    ln_kernel<<<ROWS/8, 256>>>(x2, n2_g, n2_b, xn);
    {
        dim3 grid(DFF/64, ROWS/64);
        gemm_kernel<1,false><<<grid, 256>>>(xn, mlp_w1, mlp_b1, nullptr, hid, Dq, DFF);
    }
    {
        dim3 grid(Dq/64, ROWS/64);
        gemm_kernel<1,true><<<grid, 256>>>(hid, mlp_w2, mlp_b2, x2, out, DFF, Dq);
    }
}

// round 5
// speedup vs baseline: 1.5092x; 1.3029x over previous
#include <cuda_runtime.h>
#include <cstdint>
#include <math.h>
#include <math_constants.h>

#define Bq 16
#define Nq 256
#define Dq 256
#define Hq 8
#define HDq 32
#define PDq 4
#define RATIOq 4
#define ROWS (Bq*Nq)          // 4096
#define DFF (RATIOq*Dq)       // 1024

__device__ float g_bias[(size_t)Bq*Hq*Nq*Nq];   // [B,H,N,N]
__device__ float g_xn[(size_t)ROWS*Dq];
__device__ float g_qkv[(size_t)ROWS*3*Dq];      // [B,N,3,H,HD]
__device__ float g_attout[(size_t)ROWS*Dq];
__device__ float g_x2[(size_t)ROWS*Dq];
__device__ float g_hid[(size_t)ROWS*DFF];

__device__ __forceinline__ float gelu_f(float x) {
    return 0.5f * x * (1.0f + erff(x * 0.70710678118654752f));
}

__device__ __forceinline__ float tf32r(float x) {
    uint32_t o;
    asm("cvt.rna.tf32.f32 %0, %1;" : "=r"(o) : "f"(x));
    return __uint_as_float(o);
}

__device__ __forceinline__ void mma_tf32(float c[4],
    uint32_t a0, uint32_t a1, uint32_t a2, uint32_t a3,
    uint32_t b0, uint32_t b1)
{
    asm("mma.sync.aligned.m16n8k8.row.col.f32.tf32.tf32.f32 "
        "{%0,%1,%2,%3}, {%4,%5,%6,%7}, {%8,%9}, {%0,%1,%2,%3};\n"
        : "+f"(c[0]), "+f"(c[1]), "+f"(c[2]), "+f"(c[3])
        : "r"(a0), "r"(a1), "r"(a2), "r"(a3), "r"(b0), "r"(b1));
}

// ---------------- Kernel 1: pairwise bias MLP (tf32 tensor core layer-2) -----
#define W2_STR 72
#define H1_STR 68
__global__ void __launch_bounds__(256, 2) pairwise_kernel(
    const float* __restrict__ u,
    const float* __restrict__ w1, const float* __restrict__ b1,
    const float* __restrict__ w2, const float* __restrict__ b2,
    const float* __restrict__ w3, const float* __restrict__ b3)
{
    extern __shared__ float sm[];
    float* w2s = sm;                    // 64*72
    float* h1s = sm + 64*W2_STR;        // 256*68

    __shared__ float w1s[4*64];
    __shared__ float b1s[64];
    __shared__ float b2s[64];
    __shared__ float w3s[64*8];
    __shared__ float b3s[8];

    int tid = threadIdx.x;
    int lane = tid & 31, w = tid >> 5;
    int tg = lane >> 2;
    int tr = lane & 3;

    w1s[tid] = w1[tid];
    if (tid < 64) { b1s[tid] = b1[tid]; b2s[tid] = b2[tid]; }
    w3s[tid] = w3[tid]; w3s[tid + 256] = w3[tid + 256];
    if (tid < 8) b3s[tid] = b3[tid];
    #pragma unroll
    for (int i = tid; i < 4096; i += 256) {
        int k = i >> 6, n = i & 63;
        w2s[k*W2_STR + n] = tf32r(w2[i]);
    }
    __syncthreads();

    int pos0 = blockIdx.x * 256;
    float4 uv = reinterpret_cast<const float4*>(u)[pos0 + tid];
    #pragma unroll
    for (int k4 = 0; k4 < 16; k4++) {
        float4 hv;
        float* hp = &hv.x;
        #pragma unroll
        for (int q = 0; q < 4; q++) {
            int k = k4*4 + q;
            float a = b1s[k];
            a = fmaf(uv.x, w1s[k],       a);
            a = fmaf(uv.y, w1s[64 + k],  a);
            a = fmaf(uv.z, w1s[128 + k], a);
            a = fmaf(uv.w, w1s[192 + k], a);
            hp[q] = tf32r(gelu_f(a));
        }
        *reinterpret_cast<float4*>(&h1s[tid*H1_STR + k4*4]) = hv;
    }
    __syncwarp();

    int rbase = w * 32;
    float outA[4][8];
    #pragma unroll
    for (int r = 0; r < 4; r++)
        #pragma unroll
        for (int h = 0; h < 8; h++) outA[r][h] = 0.f;

    #pragma unroll
    for (int nt = 0; nt < 8; nt++) {
        float c[2][4];
        #pragma unroll
        for (int mt = 0; mt < 2; mt++)
            #pragma unroll
            for (int q = 0; q < 4; q++) c[mt][q] = 0.f;

        #pragma unroll
        for (int kt = 0; kt < 8; kt++) {
            uint32_t bf0 = __float_as_uint(w2s[(kt*8 + tr    )*W2_STR + nt*8 + tg]);
            uint32_t bf1 = __float_as_uint(w2s[(kt*8 + tr + 4)*W2_STR + nt*8 + tg]);
            #pragma unroll
            for (int mt = 0; mt < 2; mt++) {
                int r = rbase + mt*16 + tg;
                uint32_t a0 = __float_as_uint(h1s[ r     *H1_STR + kt*8 + tr    ]);
                uint32_t a1 = __float_as_uint(h1s[(r + 8)*H1_STR + kt*8 + tr    ]);
                uint32_t a2 = __float_as_uint(h1s[ r     *H1_STR + kt*8 + tr + 4]);
                uint32_t a3 = __float_as_uint(h1s[(r + 8)*H1_STR + kt*8 + tr + 4]);
                mma_tf32(c[mt], a0, a1, a2, a3, bf0, bf1);
            }
        }
        #pragma unroll
        for (int cc = 0; cc < 2; cc++) {
            int n = nt*8 + 2*tr + cc;
            float b2n = b2s[n];
            float4 w3a = *reinterpret_cast<const float4*>(&w3s[n*8]);
            float4 w3b = *reinterpret_cast<const float4*>(&w3s[n*8 + 4]);
            #pragma unroll
            for (int mt = 0; mt < 2; mt++) {
                float glo = gelu_f(c[mt][cc]     + b2n);
                float ghi = gelu_f(c[mt][cc + 2] + b2n);
                float* olo = outA[mt*2 + 0];
                float* ohi = outA[mt*2 + 1];
                olo[0] = fmaf(glo, w3a.x, olo[0]); olo[1] = fmaf(glo, w3a.y, olo[1]);
                olo[2] = fmaf(glo, w3a.z, olo[2]); olo[3] = fmaf(glo, w3a.w, olo[3]);
                olo[4] = fmaf(glo, w3b.x, olo[4]); olo[5] = fmaf(glo, w3b.y, olo[5]);
                olo[6] = fmaf(glo, w3b.z, olo[6]); olo[7] = fmaf(glo, w3b.w, olo[7]);
                ohi[0] = fmaf(ghi, w3a.x, ohi[0]); ohi[1] = fmaf(ghi, w3a.y, ohi[1]);
                ohi[2] = fmaf(ghi, w3a.z, ohi[2]); ohi[3] = fmaf(ghi, w3a.w, ohi[3]);
                ohi[4] = fmaf(ghi, w3b.x, ohi[4]); ohi[5] = fmaf(ghi, w3b.y, ohi[5]);
                ohi[6] = fmaf(ghi, w3b.z, ohi[6]); ohi[7] = fmaf(ghi, w3b.w, ohi[7]);
            }
        }
    }

    #pragma unroll
    for (int rr = 0; rr < 4; rr++) {
        int mt = rr >> 1, hi = rr & 1;
        int lpos = rbase + mt*16 + tg + hi*8;
        int pos = pos0 + lpos;
        #pragma unroll
        for (int h = 0; h < 8; h++) {
            float v = outA[rr][h];
            v += __shfl_xor_sync(0xffffffffu, v, 1);
            v += __shfl_xor_sync(0xffffffffu, v, 2);
            outA[rr][h] = v;
        }
        int b  = pos >> 16;
        int ij = pos & 65535;
        size_t base = ((size_t)b * 8) * 65536 + (size_t)ij;
        int h0 = 2*tr;
        g_bias[base + (size_t)(h0    )*65536] = gelu_f(outA[rr][h0    ] + b3s[h0    ]);
        g_bias[base + (size_t)(h0 + 1)*65536] = gelu_f(outA[rr][h0 + 1] + b3s[h0 + 1]);
    }
}

// ---------------- Kernel 2: LayerNorm ----------------------------------------
__global__ void ln_kernel(const float* __restrict__ x,
                          const float* __restrict__ gg, const float* __restrict__ bb,
                          float* __restrict__ y)
{
    int w = threadIdx.x >> 5, lane = threadIdx.x & 31;
    int row = blockIdx.x * 8 + w;
    const float4* xr = reinterpret_cast<const float4*>(x + (size_t)row * 256);
    float4 a = xr[lane*2], c = xr[lane*2 + 1];
    float s = a.x + a.y + a.z + a.w + c.x + c.y + c.z + c.w;
    #pragma unroll
    for (int o = 16; o; o >>= 1) s += __shfl_xor_sync(0xffffffffu, s, o);
    float mu = s * (1.0f / 256.0f);
    float dx[8] = {a.x-mu, a.y-mu, a.z-mu, a.w-mu, c.x-mu, c.y-mu, c.z-mu, c.w-mu};
    float ss = 0.f;
    #pragma unroll
    for (int q = 0; q < 8; q++) ss += dx[q]*dx[q];
    #pragma unroll
    for (int o = 16; o; o >>= 1) ss += __shfl_xor_sync(0xffffffffu, ss, o);
    float rstd = rsqrtf(ss * (1.0f/256.0f) + 1e-5f);
    const float4* gr = reinterpret_cast<const float4*>(gg);
    const float4* br = reinterpret_cast<const float4*>(bb);
    float4 g0 = gr[lane*2], g1 = gr[lane*2+1];
    float4 b0 = br[lane*2], b1 = br[lane*2+1];
    float4 o0, o1;
    o0.x = fmaf(dx[0]*rstd, g0.x, b0.x); o0.y = fmaf(dx[1]*rstd, g0.y, b0.y);
    o0.z = fmaf(dx[2]*rstd, g0.z, b0.z); o0.w = fmaf(dx[3]*rstd, g0.w, b0.w);
    o1.x = fmaf(dx[4]*rstd, g1.x, b1.x); o1.y = fmaf(dx[5]*rstd, g1.y, b1.y);
    o1.z = fmaf(dx[6]*rstd, g1.z, b1.z); o1.w = fmaf(dx[7]*rstd, g1.w, b1.w);
    float4* yr = reinterpret_cast<float4*>(y + (size_t)row * 256);
    yr[lane*2] = o0; yr[lane*2 + 1] = o1;
}

// ---------------- Kernel 3: tf32 tensor-core GEMM ----------------------------
// C[M,Nc] = act(A[M,K] @ W[K,Nc] + bias) (+res). BM=128 BN=64 BK=32, 8 warps.
// Warp grid 4x2 (wm 32 rows, wn 32 cols); per warp 2x4 m16n8k8 tiles, 4 k-steps.
template<int ACT, bool RES>
__global__ void __launch_bounds__(256) gemm_tc(
    const float* __restrict__ A, const float* __restrict__ W,
    const float* __restrict__ bias, const float* __restrict__ res,
    float* __restrict__ C, int K, int Nc)
{
    __shared__ float As[128*36];
    __shared__ float Bs[32*72];
    int tid = threadIdx.x;
    int lane = tid & 31, warp = tid >> 5;
    int tg = lane >> 2, tr = lane & 3;
    int wm = warp & 3, wn = warp >> 2;
    int row0 = blockIdx.y * 128, col0 = blockIdx.x * 64;

    float c[2][4][4];
    #pragma unroll
    for (int mt = 0; mt < 2; mt++)
        #pragma unroll
        for (int nt = 0; nt < 4; nt++)
            #pragma unroll
            for (int q = 0; q < 4; q++) c[mt][nt][q] = 0.f;

    int ar = tid >> 1, ah = (tid & 1) * 16;
    int br = tid >> 3, bc = (tid & 7) * 8;
    const float* Ap = A + (size_t)(row0 + ar) * K + ah;
    const float* Wp = W + (size_t)br * Nc + col0 + bc;

    for (int k0 = 0; k0 < K; k0 += 32) {
        float4 av[4];
        #pragma unroll
        for (int q = 0; q < 4; q++) av[q] = *reinterpret_cast<const float4*>(Ap + k0 + q*4);
        float4 bv0 = *reinterpret_cast<const float4*>(Wp + (size_t)k0 * Nc);
        float4 bv1 = *reinterpret_cast<const float4*>(Wp + (size_t)k0 * Nc + 4);
        #pragma unroll
        for (int q = 0; q < 4; q++) {
            av[q].x = tf32r(av[q].x); av[q].y = tf32r(av[q].y);
            av[q].z = tf32r(av[q].z); av[q].w = tf32r(av[q].w);
            *reinterpret_cast<float4*>(&As[ar*36 + ah + q*4]) = av[q];
        }
        bv0.x = tf32r(bv0.x); bv0.y = tf32r(bv0.y); bv0.z = tf32r(bv0.z); bv0.w = tf32r(bv0.w);
        bv1.x = tf32r(bv1.x); bv1.y = tf32r(bv1.y); bv1.z = tf32r(bv1.z); bv1.w = tf32r(bv1.w);
        *reinterpret_cast<float4*>(&Bs[br*72 + bc])     = bv0;
        *reinterpret_cast<float4*>(&Bs[br*72 + bc + 4]) = bv1;
        __syncthreads();

        #pragma unroll
        for (int kk = 0; kk < 4; kk++) {
            uint32_t bf0[4], bf1[4];
            #pragma unroll
            for (int nt = 0; nt < 4; nt++) {
                bf0[nt] = __float_as_uint(Bs[(kk*8 + tr    )*72 + wn*32 + nt*8 + tg]);
                bf1[nt] = __float_as_uint(Bs[(kk*8 + tr + 4)*72 + wn*32 + nt*8 + tg]);
            }
            #pragma unroll
            for (int mt = 0; mt < 2; mt++) {
                int rr = wm*32 + mt*16 + tg;
                uint32_t fa0 = __float_as_uint(As[ rr     *36 + kk*8 + tr    ]);
                uint32_t fa1 = __float_as_uint(As[(rr + 8)*36 + kk*8 + tr    ]);
                uint32_t fa2 = __float_as_uint(As[ rr     *36 + kk*8 + tr + 4]);
                uint32_t fa3 = __float_as_uint(As[(rr + 8)*36 + kk*8 + tr + 4]);
                #pragma unroll
                for (int nt = 0; nt < 4; nt++)
                    mma_tf32(c[mt][nt], fa0, fa1, fa2, fa3, bf0[nt], bf1[nt]);
            }
        }
        __syncthreads();
    }

    #pragma unroll
    for (int mt = 0; mt < 2; mt++) {
        int r_lo = row0 + wm*32 + mt*16 + tg;
        #pragma unroll
        for (int nt = 0; nt < 4; nt++) {
            int cc0 = col0 + wn*32 + nt*8 + 2*tr;
            float bx = bias[cc0], by = bias[cc0 + 1];
            float v00 = c[mt][nt][0] + bx, v01 = c[mt][nt][1] + by;
            float v10 = c[mt][nt][2] + bx, v11 = c[mt][nt][3] + by;
            if (ACT == 1) { v00 = gelu_f(v00); v01 = gelu_f(v01); v10 = gelu_f(v10); v11 = gelu_f(v11); }
            if (RES) {
                v00 += res[(size_t)r_lo * Nc + cc0];     v01 += res[(size_t)r_lo * Nc + cc0 + 1];
                v10 += res[(size_t)(r_lo+8) * Nc + cc0]; v11 += res[(size_t)(r_lo+8) * Nc + cc0 + 1];
            }
            *reinterpret_cast<float2*>(&C[(size_t)r_lo * Nc + cc0])     = make_float2(v00, v01);
            *reinterpret_cast<float2*>(&C[(size_t)(r_lo+8) * Nc + cc0]) = make_float2(v10, v11);
        }
    }
}

// ---------------- Kernel 4: fused attention (2 query rows per warp) ----------
__global__ void attn_kernel(const unsigned char* __restrict__ mask)
{
    extern __shared__ float sm[];
    float* kT = sm;                   // [32][256]
    float* vS = sm + 32*256;          // [256][33]
    float* pS = vS + 256*33;          // [16][256]

    int bh = blockIdx.x;
    int b = bh >> 3, h = bh & 7;
    int tid = threadIdx.x;
    int w = tid >> 5, lane = tid & 31;

    const float* kp = g_qkv + ((size_t)(b*256 + tid)) * 768 + 256 + h*32;
    const float* vp = kp + 256;
    #pragma unroll
    for (int q = 0; q < 8; q++) {
        float4 kv = *reinterpret_cast<const float4*>(kp + q*4);
        kT[(q*4+0)*256 + tid] = kv.x;
        kT[(q*4+1)*256 + tid] = kv.y;
        kT[(q*4+2)*256 + tid] = kv.z;
        kT[(q*4+3)*256 + tid] = kv.w;
        float4 vv = *reinterpret_cast<const float4*>(vp + q*4);
        vS[tid*33 + q*4 + 0] = vv.x;
        vS[tid*33 + q*4 + 1] = vv.y;
        vS[tid*33 + q*4 + 2] = vv.z;
        vS[tid*33 + q*4 + 3] = vv.w;
    }
    __syncthreads();

    const float isq = 0.17677669529663689f;
    const unsigned char* mp = mask + b*256;
    uchar4 m0 = *reinterpret_cast<const uchar4*>(mp + lane*4);
    uchar4 m1 = *reinterpret_cast<const uchar4*>(mp + 128 + lane*4);

    int t0 = blockIdx.y * 64;
    for (int t = 0; t < 4; t++) {
        int r0 = t0 + t*16 + w*2;   // rows r0, r0+1
        const float* qp0 = g_qkv + ((size_t)(b*256 + r0)) * 768 + h*32;
        const float* qp1 = qp0 + 768;
        float qr0[32], qr1[32];
        #pragma unroll
        for (int q = 0; q < 8; q++) {
            float4 f0 = *reinterpret_cast<const float4*>(qp0 + q*4);
            qr0[q*4+0] = f0.x; qr0[q*4+1] = f0.y; qr0[q*4+2] = f0.z; qr0[q*4+3] = f0.w;
            float4 f1 = *reinterpret_cast<const float4*>(qp1 + q*4);
            qr1[q*4+0] = f1.x; qr1[q*4+1] = f1.y; qr1[q*4+2] = f1.z; qr1[q*4+3] = f1.w;
        }
        float a0[8], a1[8];
        #pragma unroll
        for (int c = 0; c < 8; c++) { a0[c] = 0.f; a1[c] = 0.f; }
        #pragma unroll
        for (int hd = 0; hd < 32; hd++) {
            float4 k0 = *reinterpret_cast<const float4*>(&kT[hd*256 + lane*4]);
            float4 k1 = *reinterpret_cast<const float4*>(&kT[hd*256 + 128 + lane*4]);
            float q0 = qr0[hd], q1 = qr1[hd];
            a0[0] = fmaf(q0, k0.x, a0[0]); a0[1] = fmaf(q0, k0.y, a0[1]);
            a0[2] = fmaf(q0, k0.z, a0[2]); a0[3] = fmaf(q0, k0.w, a0[3]);
            a0[4] = fmaf(q0, k1.x, a0[4]); a0[5] = fmaf(q0, k1.y, a0[5]);
            a0[6] = fmaf(q0, k1.z, a0[6]); a0[7] = fmaf(q0, k1.w, a0[7]);
            a1[0] = fmaf(q1, k0.x, a1[0]); a1[1] = fmaf(q1, k0.y, a1[1]);
            a1[2] = fmaf(q1, k0.z, a1[2]); a1[3] = fmaf(q1, k0.w, a1[3]);
            a1[4] = fmaf(q1, k1.x, a1[4]); a1[5] = fmaf(q1, k1.y, a1[5]);
            a1[6] = fmaf(q1, k1.z, a1[6]); a1[7] = fmaf(q1, k1.w, a1[7]);
        }

        #pragma unroll
        for (int rr = 0; rr < 2; rr++) {
            float* acc = rr ? a1 : a0;
            int i = r0 + rr;
            const float* bp = g_bias + ((size_t)bh * 256 + i) * 256;
            float4 bb0 = *reinterpret_cast<const float4*>(bp + lane*4);
            float4 bb1 = *reinterpret_cast<const float4*>(bp + 128 + lane*4);
            float l[8];
            l[0] = fmaf(acc[0], isq, bb0.x); l[1] = fmaf(acc[1], isq, bb0.y);
            l[2] = fmaf(acc[2], isq, bb0.z); l[3] = fmaf(acc[3], isq, bb0.w);
            l[4] = fmaf(acc[4], isq, bb1.x); l[5] = fmaf(acc[5], isq, bb1.y);
            l[6] = fmaf(acc[6], isq, bb1.z); l[7] = fmaf(acc[7], isq, bb1.w);
            if (m0.x) l[0] = -CUDART_INF_F; if (m0.y) l[1] = -CUDART_INF_F;
            if (m0.z) l[2] = -CUDART_INF_F; if (m0.w) l[3] = -CUDART_INF_F;
            if (m1.x) l[4] = -CUDART_INF_F; if (m1.y) l[5] = -CUDART_INF_F;
            if (m1.z) l[6] = -CUDART_INF_F; if (m1.w) l[7] = -CUDART_INF_F;

            float mx = l[0];
            #pragma unroll
            for (int c = 1; c < 8; c++) mx = fmaxf(mx, l[c]);
            #pragma unroll
            for (int o = 16; o; o >>= 1) mx = fmaxf(mx, __shfl_xor_sync(0xffffffffu, mx, o));
            float e[8], s = 0.f;
            #pragma unroll
            for (int c = 0; c < 8; c++) { e[c] = expf(l[c] - mx); s += e[c]; }
            #pragma unroll
            for (int o = 16; o; o >>= 1) s += __shfl_xor_sync(0xffffffffu, s, o);
            float inv = 1.0f / s;
            int pr = w*2 + rr;
            *reinterpret_cast<float4*>(&pS[pr*256 + lane*4]) =
                make_float4(e[0]*inv, e[1]*inv, e[2]*inv, e[3]*inv);
            *reinterpret_cast<float4*>(&pS[pr*256 + 128 + lane*4]) =
                make_float4(e[4]*inv, e[5]*inv, e[6]*inv, e[7]*inv);
        }
        __syncwarp();

        // PV: lane = hd; share vS loads across the 2 rows
        float o0 = 0.f, o1 = 0.f;
        #pragma unroll 8
        for (int j4 = 0; j4 < 64; j4++) {
            float4 p0 = *reinterpret_cast<const float4*>(&pS[(w*2    )*256 + j4*4]);
            float4 p1 = *reinterpret_cast<const float4*>(&pS[(w*2 + 1)*256 + j4*4]);
            float v0 = vS[(j4*4+0)*33 + lane];
            float v1 = vS[(j4*4+1)*33 + lane];
            float v2 = vS[(j4*4+2)*33 + lane];
            float v3 = vS[(j4*4+3)*33 + lane];
            o0 = fmaf(p0.x, v0, o0); o0 = fmaf(p0.y, v1, o0);
            o0 = fmaf(p0.z, v2, o0); o0 = fmaf(p0.w, v3, o0);
            o1 = fmaf(p1.x, v0, o1); o1 = fmaf(p1.y, v1, o1);
            o1 = fmaf(p1.z, v2, o1); o1 = fmaf(p1.w, v3, o1);
        }
        g_attout[((size_t)(b*256 + r0    )) * 256 + h*32 + lane] = o0;
        g_attout[((size_t)(b*256 + r0 + 1)) * 256 + h*32 + lane] = o1;
        __syncwarp();
    }
}

// ---------------- launch ------------------------------------------------------
extern "C" void kernel_launch(void* const* d_in, const int* in_sizes, int n_in,
                              void* d_out, int out_size)
{
    const float* x      = (const float*)d_in[0];
    const float* u      = (const float*)d_in[1];
    const unsigned char* mask = (const unsigned char*)d_in[2];
    const float* n1_g   = (const float*)d_in[3];
    const float* n1_b   = (const float*)d_in[4];
    const float* qkv_w  = (const float*)d_in[5];
    const float* qkv_b  = (const float*)d_in[6];
    const float* proj_w = (const float*)d_in[7];
    const float* proj_b = (const float*)d_in[8];
    const float* n2_g   = (const float*)d_in[9];
    const float* n2_b   = (const float*)d_in[10];
    const float* mlp_w1 = (const float*)d_in[11];
    const float* mlp_b1 = (const float*)d_in[12];
    const float* mlp_w2 = (const float*)d_in[13];
    const float* mlp_b2 = (const float*)d_in[14];
    const float* pw_w1  = (const float*)d_in[15];
    const float* pw_b1  = (const float*)d_in[16];
    const float* pw_w2  = (const float*)d_in[17];
    const float* pw_b2  = (const float*)d_in[18];
    const float* pw_w3  = (const float*)d_in[19];
    const float* pw_b3  = (const float*)d_in[20];
    float* out = (float*)d_out;

    float* xn  = nullptr; float* qkv = nullptr; float* ao = nullptr;
    float* x2  = nullptr; float* hid = nullptr;
    cudaGetSymbolAddress((void**)&xn,  g_xn);
    cudaGetSymbolAddress((void**)&qkv, g_qkv);
    cudaGetSymbolAddress((void**)&ao,  g_attout);
    cudaGetSymbolAddress((void**)&x2,  g_x2);
    cudaGetSymbolAddress((void**)&hid, g_hid);

    // 1) pairwise bias MLP
    {
        int smem = (64*W2_STR + 256*H1_STR) * (int)sizeof(float);
        cudaFuncSetAttribute(pairwise_kernel, cudaFuncAttributeMaxDynamicSharedMemorySize, smem);
        pairwise_kernel<<<Bq*Nq*Nq/256, 256, smem>>>(u, pw_w1, pw_b1, pw_w2, pw_b2, pw_w3, pw_b3);
    }

    // 2) LN1 + qkv GEMM
    ln_kernel<<<ROWS/8, 256>>>(x, n1_g, n1_b, xn);
    gemm_tc<0,false><<<dim3(3*Dq/64, ROWS/128), 256>>>(xn, qkv_w, qkv_b, nullptr, qkv, Dq, 3*Dq);

    // 3) attention
    {
        int smem = (32*256 + 256*33 + 16*256) * (int)sizeof(float);
        cudaFuncSetAttribute(attn_kernel, cudaFuncAttributeMaxDynamicSharedMemorySize, smem);
        dim3 grid(Bq*Hq, 4);
        attn_kernel<<<grid, 256, smem>>>(mask);
    }

    // 4) proj + residual
    gemm_tc<0,true><<<dim3(Dq/64, ROWS/128), 256>>>(ao, proj_w, proj_b, x, x2, Dq, Dq);

    // 5) LN2 + MLP
    ln_kernel<<<ROWS/8, 256>>>(x2, n2_g, n2_b, xn);
    gemm_tc<1,false><<<dim3(DFF/64, ROWS/128), 256>>>(xn, mlp_w1, mlp_b1, nullptr, hid, Dq, DFF);
    gemm_tc<1,true><<<dim3(Dq/64, ROWS/128), 256>>>(hid, mlp_w2, mlp_b2, x2, out, DFF, Dq);
}